// round 11
// baseline (speedup 1.0000x reference)
#include <cuda_runtime.h>
#include <cuda_fp16.h>
#include <cstdint>

#define N_TASKS   8
#define D_MODEL   1024
#define HIDDEN    1024
#define N_CLASSES 100
#define BATCH     8192
#define KDIM      1024
#define LDSA      72            // A smem row stride (halves): 64 + 8
#define LDSB      136           // B smem row stride (halves): 128 + 8
#define STAGES    3
#define GRID1     296           // persistent CTAs (148 SMs x 2)
#define GRID2     296

// ===================== device scratch =====================
__device__ int g_count[N_TASKS], g_offset[N_TASKS];
__device__ __align__(16) int g_rows[BATCH];
__device__ int g_mt_task[80], g_mt_m0[80], g_nmt;      // gemm1 128-row m-tiles
__device__ int g_mt2_task[160], g_mt2_m0[160], g_nmt2; // gemm2 64-row m-tiles
__device__ int g_tile_ctr, g_tile_ctr2;
__device__ __align__(256) __half g_xh[(BATCH + 128) * KDIM];      // grouped x fp16 [m][k]
__device__ __align__(256) __half g_w1h[N_TASKS * KDIM * HIDDEN];  // W1 fp16 native [t][k][n]
__device__ __align__(256) __half g_w2h[N_TASKS * KDIM * 128];     // W2 fp16 [t][k][n pad]
__device__ __align__(256) __half g_hh[(BATCH + 128) * KDIM];      // grouped h fp16 [m][k]

// ===================== helpers =====================
__device__ __forceinline__ uint32_t smem_u32(const void* p) {
    uint32_t a;
    asm("{ .reg .u64 t; cvta.to.shared.u64 t, %1; cvt.u32.u64 %0, t; }" : "=r"(a) : "l"(p));
    return a;
}
__device__ __forceinline__ void ldm4(uint32_t& r0, uint32_t& r1, uint32_t& r2, uint32_t& r3,
                                     uint32_t addr) {
    asm volatile("ldmatrix.sync.aligned.m8n8.x4.shared.b16 {%0,%1,%2,%3}, [%4];"
                 : "=r"(r0), "=r"(r1), "=r"(r2), "=r"(r3) : "r"(addr));
}
__device__ __forceinline__ void ldm4t(uint32_t& r0, uint32_t& r1, uint32_t& r2, uint32_t& r3,
                                      uint32_t addr) {
    asm volatile("ldmatrix.sync.aligned.m8n8.x4.trans.shared.b16 {%0,%1,%2,%3}, [%4];"
                 : "=r"(r0), "=r"(r1), "=r"(r2), "=r"(r3) : "r"(addr));
}
__device__ __forceinline__ void mma16816(float* c, const uint32_t* a, const uint32_t* b) {
    asm volatile(
        "mma.sync.aligned.m16n8k16.row.col.f32.f16.f16.f32 "
        "{%0,%1,%2,%3}, {%4,%5,%6,%7}, {%8,%9}, {%0,%1,%2,%3};"
        : "+f"(c[0]), "+f"(c[1]), "+f"(c[2]), "+f"(c[3])
        : "r"(a[0]), "r"(a[1]), "r"(a[2]), "r"(a[3]), "r"(b[0]), "r"(b[1]));
}
__device__ __forceinline__ void cp16(uint32_t dst, const void* src) {
    asm volatile("cp.async.cg.shared.global [%0], [%1], 16;" :: "r"(dst), "l"(src) : "memory");
}
#define CP_COMMIT() asm volatile("cp.async.commit_group;" ::: "memory")
#define CP_WAIT1()  asm volatile("cp.async.wait_group 1;" ::: "memory")
#define CP_WAIT0()  asm volatile("cp.async.wait_group 0;" ::: "memory")

// ===================== grouping + tile tables (one CTA) =====================
__global__ __launch_bounds__(1024)
void group_kernel(const int* __restrict__ task_id) {
    __shared__ int cnt[N_TASKS], offs[N_TASKS], cur[N_TASKS];
    const int tid = threadIdx.x;
    if (tid < N_TASKS) { cnt[tid] = 0; cur[tid] = 0; }
    __syncthreads();
    int ids[8];
#pragma unroll
    for (int i = 0; i < 8; i++) {
        ids[i] = task_id[tid * 8 + i];
        atomicAdd(&cnt[ids[i]], 1);
    }
    __syncthreads();
    if (tid == 0) {
        int a = 0, nm = 0, nm2 = 0;
        for (int t = 0; t < N_TASKS; t++) {
            offs[t] = a; g_offset[t] = a; g_count[t] = cnt[t];
            for (int m0 = 0; m0 < cnt[t]; m0 += 128) {
                g_mt_task[nm] = t; g_mt_m0[nm] = m0; nm++;
            }
            for (int m0 = 0; m0 < cnt[t]; m0 += 64) {
                if (nm2 < 160) { g_mt2_task[nm2] = t; g_mt2_m0[nm2] = m0; nm2++; }
            }
            a += cnt[t];
        }
        g_nmt = nm;
        g_nmt2 = nm2;
        g_tile_ctr = 0;
        g_tile_ctr2 = 0;
    }
    __syncthreads();
#pragma unroll
    for (int i = 0; i < 8; i++) {
        int t = ids[i];
        int p = atomicAdd(&cur[t], 1);
        g_rows[offs[t] + p] = tid * 8 + i;
    }
}

// ===================== fused conversions + out init: one kernel, 4 regions =====================
#define W1_BLKS 4096      // 8M floats / (256*8)
#define W2_BLKS 512
#define X_BLKS  2048      // 8192 rows / 4
#define OUT_BLKS 800      // 819200 floats / (256*4)
__global__ void convert_all(const float* __restrict__ x,
                            const float* __restrict__ W1,
                            const float* __restrict__ W2,
                            const int* __restrict__ task_id,
                            const float* __restrict__ b2,
                            float* __restrict__ out) {
    const int bid = blockIdx.x;
    const int tid = threadIdx.x;
    if (bid < W1_BLKS) {
        const size_t i = ((size_t)bid * 256 + tid) * 8;
        float4 v0 = ((const float4*)(W1 + i))[0];
        float4 v1 = ((const float4*)(W1 + i))[1];
        __half2 o[4];
        o[0] = __halves2half2(__float2half(v0.x), __float2half(v0.y));
        o[1] = __halves2half2(__float2half(v0.z), __float2half(v0.w));
        o[2] = __halves2half2(__float2half(v1.x), __float2half(v1.y));
        o[3] = __halves2half2(__float2half(v1.z), __float2half(v1.w));
        *(uint4*)(g_w1h + i) = *(uint4*)o;
    } else if (bid < W1_BLKS + W2_BLKS) {
        const size_t e = ((size_t)(bid - W1_BLKS) * 256 + tid) * 8;
        const int rk = (int)(e >> 7);
        const int n0 = (int)(e & 127);
        const float* src = W2 + (size_t)rk * N_CLASSES;
        __half2 o[4];
#pragma unroll
        for (int j = 0; j < 4; j++) {
            int na = n0 + 2 * j, nb = n0 + 2 * j + 1;
            float fa = (na < N_CLASSES) ? src[na] : 0.f;
            float fb = (nb < N_CLASSES) ? src[nb] : 0.f;
            o[j] = __halves2half2(__float2half(fa), __float2half(fb));
        }
        *(uint4*)(g_w2h + (size_t)rk * 128 + n0) = *(uint4*)o;
    } else if (bid < W1_BLKS + W2_BLKS + X_BLKS) {
        const int lrow = tid >> 6;
        const int j    = tid & 63;
        const int b    = (bid - W1_BLKS - W2_BLKS) * 4 + lrow;
        const int r    = g_rows[b];
        const float* src = x + (size_t)r * D_MODEL + j * 16;
        float4 v0 = ((const float4*)src)[0];
        float4 v1 = ((const float4*)src)[1];
        float4 v2 = ((const float4*)src)[2];
        float4 v3 = ((const float4*)src)[3];
        __half2 o[8];
        o[0] = __halves2half2(__float2half(v0.x), __float2half(v0.y));
        o[1] = __halves2half2(__float2half(v0.z), __float2half(v0.w));
        o[2] = __halves2half2(__float2half(v1.x), __float2half(v1.y));
        o[3] = __halves2half2(__float2half(v1.z), __float2half(v1.w));
        o[4] = __halves2half2(__float2half(v2.x), __float2half(v2.y));
        o[5] = __halves2half2(__float2half(v2.z), __float2half(v2.w));
        o[6] = __halves2half2(__float2half(v3.x), __float2half(v3.y));
        o[7] = __halves2half2(__float2half(v3.z), __float2half(v3.w));
        uint4* dst = (uint4*)(g_xh + (size_t)b * KDIM + j * 16);
        dst[0] = ((uint4*)o)[0];
        dst[1] = ((uint4*)o)[1];
    } else {
        // out init: out[b][n] = b2[task[b]][n]
        const int e0 = ((bid - W1_BLKS - W2_BLKS - X_BLKS) * 256 + tid) * 4;
#pragma unroll
        for (int i = 0; i < 4; i++) {
            int e = e0 + i;
            int b = e / N_CLASSES, n = e - b * N_CLASSES;
            out[e] = b2[task_id[b] * N_CLASSES + n];
        }
    }
}

// ===================== GEMM core: BM x BN tile, KCH chunks of 64 =====================
template<int BM, int BN, int BSTRIDE, int KCH>
__device__ __forceinline__ void gemm_core(
    const __half* __restrict__ gA, const __half* __restrict__ gB,
    char* smem, float c[BM / 32][BN / 32][4])
{
    constexpr int MI = BM / 32, NI = BN / 32;
    constexpr int A_BYTES = BM * LDSA * 2;
    constexpr int B_BYTES = 64 * LDSB * 2;
    constexpr int STAGE_B = A_BYTES + B_BYTES;
    constexpr int UNITS_A = BM * 8;
    constexpr int UNITS_B = 64 * (BN / 8);
    constexpr int UNITS = UNITS_A + UNITS_B;

    const int tid  = threadIdx.x;
    const int lane = tid & 31;
    const int wid  = tid >> 5;
    const int wm   = wid & 1;
    const int wn   = wid >> 1;
    const uint32_t smem0 = smem_u32(smem);

    uint32_t eA[MI], eB[NI / 2];
#pragma unroll
    for (int mi = 0; mi < MI; mi++)
        eA[mi] = ((wm * (BM / 2) + mi * 16 + (lane & 15)) * LDSA + (lane >> 4) * 8) * 2;
    {
        const int g = lane >> 3, r = lane & 7;
        const int kl = (g & 1) * 8 + r;
#pragma unroll
        for (int j = 0; j < NI / 2; j++)
            eB[j] = (kl * LDSB + wn * (BN / 4) + j * 16 + (g >> 1) * 8) * 2;
    }

    auto issue = [&](int ch, int stage) {
        const int k = ch * 64;
        const uint32_t dA = smem0 + stage * STAGE_B;
        const uint32_t dB = dA + A_BYTES;
#pragma unroll
        for (int u = tid; u < UNITS; u += 256) {
            if (u < UNITS_A) {
                int row = u >> 3, seg = u & 7;
                cp16(dA + (row * LDSA + seg * 8) * 2, gA + (size_t)row * KDIM + k + seg * 8);
            } else {
                int v = u - UNITS_A;
                int kr = v / (BN / 8), seg = v % (BN / 8);
                cp16(dB + (kr * LDSB + seg * 8) * 2, gB + (size_t)(k + kr) * BSTRIDE + seg * 8);
            }
        }
    };

    issue(0, 0); CP_COMMIT();
    issue(1, 1); CP_COMMIT();

    for (int ch = 0; ch < KCH; ch++) {
        CP_WAIT1();
        __syncthreads();
        if (ch + 2 < KCH) issue(ch + 2, (ch + 2) % STAGES);
        CP_COMMIT();

        const uint32_t bA = smem0 + (ch % STAGES) * STAGE_B;
        const uint32_t bB = bA + A_BYTES;
#pragma unroll
        for (int ks = 0; ks < 4; ks++) {
            uint32_t a[MI][4], b[NI][2];
#pragma unroll
            for (int mi = 0; mi < MI; mi++)
                ldm4(a[mi][0], a[mi][1], a[mi][2], a[mi][3], bA + eA[mi] + ks * 32);
#pragma unroll
            for (int j = 0; j < NI / 2; j++) {
                uint32_t r0, r1, r2, r3;
                ldm4t(r0, r1, r2, r3, bB + eB[j] + ks * (16 * LDSB * 2));
                b[2 * j][0] = r0; b[2 * j][1] = r1;
                b[2 * j + 1][0] = r2; b[2 * j + 1][1] = r3;
            }
#pragma unroll
            for (int mi = 0; mi < MI; mi++)
#pragma unroll
                for (int ni = 0; ni < NI; ni++)
                    mma16816(c[mi][ni], a[mi], b[ni]);
        }
    }
}

// ===================== layer 1: persistent, dynamic tile queue =====================
#define SMEM1 (STAGES * (128 * LDSA + 64 * LDSB) * 2)
__global__ __launch_bounds__(256, 2)
void gemm1_mma(const float* __restrict__ b1) {
    extern __shared__ char smem[];
    __shared__ int s_tile;
    const int ntotal = g_nmt * 8;

    const int lane = threadIdx.x & 31;
    const int wid  = threadIdx.x >> 5;
    const int wm = wid & 1, wn = wid >> 1;
    const int r4 = lane >> 2, c2 = (lane & 3) * 2;

    for (;;) {
        if (threadIdx.x == 0) s_tile = atomicAdd(&g_tile_ctr, 1);
        __syncthreads();
        const int tile = s_tile;
        if (tile >= ntotal) return;
        const int e  = tile >> 3;
        const int n0 = (tile & 7) * 128;
        const int t  = g_mt_task[e];
        const int m0 = g_mt_m0[e];
        const int cnt = g_count[t];
        const int off = g_offset[t];

        float c[4][4][4];
#pragma unroll
        for (int mi = 0; mi < 4; mi++)
#pragma unroll
            for (int ni = 0; ni < 4; ni++)
#pragma unroll
                for (int r = 0; r < 4; r++) c[mi][ni][r] = 0.f;

        gemm_core<128, 128, HIDDEN, 16>(g_xh + (size_t)(off + m0) * KDIM,
                                        g_w1h + (size_t)t * KDIM * HIDDEN + n0, smem, c);

        const float* b1t = b1 + t * HIDDEN + n0;
#pragma unroll
        for (int mi = 0; mi < 4; mi++) {
#pragma unroll
            for (int half = 0; half < 2; half++) {
                const int m = m0 + wm * 64 + mi * 16 + r4 + half * 8;
                if (m < cnt) {
                    const size_t rowo = (size_t)(off + m) * KDIM;
#pragma unroll
                    for (int ni = 0; ni < 4; ni++) {
                        const int n = wn * 32 + ni * 8 + c2;
                        float v0 = fmaxf(c[mi][ni][half * 2 + 0] + b1t[n], 0.f);
                        float v1 = fmaxf(c[mi][ni][half * 2 + 1] + b1t[n + 1], 0.f);
                        *(__half2*)(g_hh + rowo + n0 + n) =
                            __halves2half2(__float2half(v0), __float2half(v1));
                    }
                }
            }
        }
        CP_WAIT0();
        __syncthreads();
    }
}

// ===================== layer 2: persistent, 64x128 tiles, split-K=4, atomic =====================
#define SMEM2 (STAGES * (64 * LDSA + 64 * LDSB) * 2)
__global__ __launch_bounds__(256, 2)
void gemm2_mma(float* __restrict__ out) {
    extern __shared__ char smem[];
    __shared__ int s_tile;
    const int ntotal = g_nmt2 * 4;

    const int lane = threadIdx.x & 31;
    const int wid  = threadIdx.x >> 5;
    const int wm = wid & 1, wn = wid >> 1;
    const int r4 = lane >> 2, c2 = (lane & 3) * 2;

    for (;;) {
        if (threadIdx.x == 0) s_tile = atomicAdd(&g_tile_ctr2, 1);
        __syncthreads();
        const int tile = s_tile;
        if (tile >= ntotal) return;
        const int e  = tile >> 2;
        const int ks = tile & 3;               // K-split: [ks*256, ks*256+256)
        const int t  = g_mt2_task[e];
        const int m0 = g_mt2_m0[e];
        const int cnt = g_count[t];
        const int off = g_offset[t];

        float c[2][4][4];
#pragma unroll
        for (int mi = 0; mi < 2; mi++)
#pragma unroll
            for (int ni = 0; ni < 4; ni++)
#pragma unroll
                for (int r = 0; r < 4; r++) c[mi][ni][r] = 0.f;

        gemm_core<64, 128, 128, 4>(g_hh + (size_t)(off + m0) * KDIM + ks * 256,
                                   g_w2h + (size_t)t * KDIM * 128 + (size_t)ks * 256 * 128,
                                   smem, c);

#pragma unroll
        for (int mi = 0; mi < 2; mi++) {
#pragma unroll
            for (int half = 0; half < 2; half++) {
                const int m = m0 + wm * 32 + mi * 16 + r4 + half * 8;
                if (m < cnt) {
                    const int ro = g_rows[off + m];
                    float* orow = out + (size_t)ro * N_CLASSES;
#pragma unroll
                    for (int ni = 0; ni < 4; ni++) {
                        const int n = wn * 32 + ni * 8 + c2;
                        if (n < N_CLASSES)
                            atomicAdd(orow + n, c[mi][ni][half * 2 + 0]);
                        if (n + 1 < N_CLASSES)
                            atomicAdd(orow + n + 1, c[mi][ni][half * 2 + 1]);
                    }
                }
            }
        }
        CP_WAIT0();
        __syncthreads();
    }
}

// ===================== launch =====================
extern "C" void kernel_launch(void* const* d_in, const int* in_sizes, int n_in,
                              void* d_out, int out_size) {
    const float* x       = (const float*)d_in[0];
    const int*   task_id = (const int*)d_in[1];
    const float* W1      = (const float*)d_in[2];
    const float* b1      = (const float*)d_in[3];
    const float* W2      = (const float*)d_in[4];
    const float* b2      = (const float*)d_in[5];
    float* out = (float*)d_out;

    static bool attr_done = false;
    if (!attr_done) {
        cudaFuncSetAttribute(gemm1_mma, cudaFuncAttributeMaxDynamicSharedMemorySize, SMEM1);
        cudaFuncSetAttribute(gemm2_mma, cudaFuncAttributeMaxDynamicSharedMemorySize, SMEM2);
        attr_done = true;
    }

    group_kernel<<<1, 1024>>>(task_id);
    convert_all<<<W1_BLKS + W2_BLKS + X_BLKS + OUT_BLKS, 256>>>(x, W1, W2, task_id, b2, out);

    gemm1_mma<<<GRID1, 256, SMEM1>>>(b1);
    gemm2_mma<<<GRID2, 256, SMEM2>>>(out);
}